// round 5
// baseline (speedup 1.0000x reference)
#include <cuda_runtime.h>
#include <cstdint>
#include <math.h>

// ---------------- problem constants ----------------
#define B_    2048
#define POOL  512
#define TOPK  4
#define TOP8  8
#define EPL   8
#define GPL   8
#define EMB   768
#define KEYD  768

// output offsets (float32 elements)
#define PK_ROWS   20
#define PK_SZ     ((size_t)B_ * PK_ROWS * EMB)
#define PV_OFF    (PK_SZ)
#define LOSS_OFF  (2 * PK_SZ)
#define CNT_OFF   (LOSS_OFF + 1)
#define XB_OFF    (CNT_OFF + POOL)   // odd offset -> only 4-byte aligned!

// ---------------- device scratch ----------------
__device__ float g_C[B_ * POOL];
__device__ float g_invq[B_];
__device__ float g_invk[POOL];
__device__ float g_partial[32 * POOL];
__device__ int   g_idx[B_ * TOPK];
__device__ int   g_cnt[POOL];

// ---------------- helpers ----------------
__device__ __forceinline__ uint32_t f2tf(float f) {
    uint32_t r;
    asm("cvt.rna.tf32.f32 %0, %1;" : "=r"(r) : "f"(f));
    return r;
}
__device__ __forceinline__ void mma_tf32(float* c, const uint32_t* a, const uint32_t* b) {
    asm volatile(
        "mma.sync.aligned.m16n8k8.row.col.f32.tf32.tf32.f32 "
        "{%0,%1,%2,%3}, {%4,%5,%6,%7}, {%8,%9}, {%0,%1,%2,%3};"
        : "+f"(c[0]), "+f"(c[1]), "+f"(c[2]), "+f"(c[3])
        : "r"(a[0]), "r"(a[1]), "r"(a[2]), "r"(a[3]), "r"(b[0]), "r"(b[1]));
}

__device__ __forceinline__ float row_invnorm(const float4* s4, int lane) {
    float ss = 0.f;
    #pragma unroll
    for (int i = 0; i < 6; i++) {
        float4 v = s4[lane + 32 * i];
        ss += v.x * v.x + v.y * v.y + v.z * v.z + v.w * v.w;
    }
    #pragma unroll
    for (int off = 16; off; off >>= 1) ss += __shfl_xor_sync(0xffffffffu, ss, off);
    return 1.0f / fmaxf(sqrtf(ss), 1e-12f);
}

// ---------------- kernels ----------------

__global__ void zero_kernel() { g_cnt[threadIdx.x] = 0; }

__global__ __launch_bounds__(256) void invnorm_q_kernel(const float* __restrict__ xq) {
    int warp = (blockIdx.x * 256 + threadIdx.x) >> 5;
    int lane = threadIdx.x & 31;
    float inv = row_invnorm((const float4*)(xq + (size_t)warp * KEYD), lane);
    if (lane == 0) g_invq[warp] = inv;
}

__global__ __launch_bounds__(256) void invnorm_k_kernel(const float* __restrict__ ek) {
    int warp = (blockIdx.x * 256 + threadIdx.x) >> 5;
    int lane = threadIdx.x & 31;
    float inv = row_invnorm((const float4*)(ek + (size_t)warp * KEYD), lane);
    if (lane == 0) g_invk[warp] = inv;
}

// tf32 GEMM: C[B_,POOL] = (xq * eK^T) * invq[m] * invk[n]
// BM=64 BN=64 BK=32, 256 threads (8 warps 2m x 4n, warp tile 32x16), double-buffered
#define BM 64
#define BN 64
#define BK 32
#define AST 72
__global__ __launch_bounds__(256) void gemm_tf32_kernel(const float* __restrict__ A,
                                                        const float* __restrict__ Bm,
                                                        float* __restrict__ C) {
    __shared__ uint32_t As[2][BK][AST];
    __shared__ uint32_t Bs[2][BK][AST];
    const int t    = threadIdx.x;
    const int lane = t & 31;
    const int wid  = t >> 5;
    const int gid  = lane >> 2;
    const int tig  = lane & 3;
    const int wm   = (wid >> 2) * 32;
    const int wn   = (wid & 3) * 16;
    const int m0   = blockIdx.y * BM;
    const int n0   = blockIdx.x * BN;

    const int arow = t >> 2;
    const int ac4  = (t & 3) * 2;
    const int rot  = t & 3;

    const float4* Ag = (const float4*)(A  + (size_t)(m0 + arow) * KEYD) + ac4;
    const float4* Bg = (const float4*)(Bm + (size_t)(n0 + arow) * KEYD) + ac4;

    float acc[2][2][4];
    #pragma unroll
    for (int i = 0; i < 2; i++)
        #pragma unroll
        for (int j = 0; j < 2; j++)
            #pragma unroll
            for (int v = 0; v < 4; v++) acc[i][j][v] = 0.f;

    float4 pa[2], pb[2];
    pa[0] = Ag[0]; pa[1] = Ag[1];
    pb[0] = Bg[0]; pb[1] = Bg[1];

    #define STORE_TILE(buf_)                                                  \
        {                                                                     \
            _Pragma("unroll")                                                 \
            for (int i = 0; i < 2; i++) {                                     \
                float ca[4] = {pa[i].x, pa[i].y, pa[i].z, pa[i].w};           \
                float cb[4] = {pb[i].x, pb[i].y, pb[i].z, pb[i].w};           \
                _Pragma("unroll")                                             \
                for (int s = 0; s < 4; s++) {                                 \
                    int rc = (s + rot) & 3;                                   \
                    As[buf_][(ac4 + i) * 4 + rc][arow] = f2tf(ca[rc]);        \
                    Bs[buf_][(ac4 + i) * 4 + rc][arow] = f2tf(cb[rc]);        \
                }                                                             \
            }                                                                 \
        }

    STORE_TILE(0);
    __syncthreads();

    const int NIT = KEYD / BK;   // 24
    for (int it = 0; it < NIT; it++) {
        int buf = it & 1;
        if (it + 1 < NIT) {
            const float4* Ag2 = Ag + (it + 1) * (BK / 4);
            const float4* Bg2 = Bg + (it + 1) * (BK / 4);
            pa[0] = Ag2[0]; pa[1] = Ag2[1];
            pb[0] = Bg2[0]; pb[1] = Bg2[1];
        }
        #pragma unroll
        for (int kk = 0; kk < BK; kk += 8) {
            uint32_t af[2][4], bf[2][2];
            #pragma unroll
            for (int mt = 0; mt < 2; mt++) {
                int mb = wm + mt * 16 + gid;
                af[mt][0] = As[buf][kk + tig][mb];
                af[mt][1] = As[buf][kk + tig][mb + 8];
                af[mt][2] = As[buf][kk + tig + 4][mb];
                af[mt][3] = As[buf][kk + tig + 4][mb + 8];
            }
            #pragma unroll
            for (int nt = 0; nt < 2; nt++) {
                int nb = wn + nt * 8 + gid;
                bf[nt][0] = Bs[buf][kk + tig][nb];
                bf[nt][1] = Bs[buf][kk + tig + 4][nb];
            }
            #pragma unroll
            for (int mt = 0; mt < 2; mt++)
                #pragma unroll
                for (int nt = 0; nt < 2; nt++)
                    mma_tf32(acc[mt][nt], af[mt], bf[nt]);
        }
        if (it + 1 < NIT) STORE_TILE(buf ^ 1);
        __syncthreads();
    }

    #pragma unroll
    for (int mt = 0; mt < 2; mt++) {
        int m = m0 + wm + mt * 16 + gid;
        float iq0 = g_invq[m], iq1 = g_invq[m + 8];
        #pragma unroll
        for (int nt = 0; nt < 2; nt++) {
            int n = n0 + wn + nt * 8 + 2 * tig;
            float ik0 = g_invk[n], ik1 = g_invk[n + 1];
            C[(size_t)m * POOL + n]           = acc[mt][nt][0] * iq0 * ik0;
            C[(size_t)m * POOL + n + 1]       = acc[mt][nt][1] * iq0 * ik1;
            C[(size_t)(m + 8) * POOL + n]     = acc[mt][nt][2] * iq1 * ik0;
            C[(size_t)(m + 8) * POOL + n + 1] = acc[mt][nt][3] * iq1 * ik1;
        }
    }
}

// block per row: warp0 approx top-8 from tf32 C; 4 warps exact-recheck 2 cands each
__global__ __launch_bounds__(128) void route_kernel(const float* __restrict__ C,
                                                    const float* __restrict__ xq,
                                                    const float* __restrict__ ek) {
    int row  = blockIdx.x;
    int t    = threadIdx.x;
    int lane = t & 31;
    int w    = t >> 5;
    __shared__ int   s_cand[TOP8];
    __shared__ float s_ex[TOP8];

    if (w == 0) {
        const float* crow = C + (size_t)row * POOL;
        float d[16];
        #pragma unroll
        for (int u = 0; u < 16; u++) d[u] = 1.0f - crow[u * 32 + lane];
        #pragma unroll
        for (int k = 0; k < TOP8; k++) {
            float best = INFINITY; int bi = 0x7fffffff;
            #pragma unroll
            for (int u = 0; u < 16; u++) {
                int p = u * 32 + lane;
                if (d[u] < best || (d[u] == best && p < bi)) { best = d[u]; bi = p; }
            }
            #pragma unroll
            for (int off = 16; off; off >>= 1) {
                float ov = __shfl_xor_sync(0xffffffffu, best, off);
                int   oi = __shfl_xor_sync(0xffffffffu, bi, off);
                if (ov < best || (ov == best && oi < bi)) { best = ov; bi = oi; }
            }
            if (lane == 0) s_cand[k] = bi;
            int ul = bi >> 5, ll = bi & 31;
            #pragma unroll
            for (int u = 0; u < 16; u++)
                if (u == ul && ll == lane) d[u] = INFINITY;
        }
    }
    __syncthreads();

    const float4* q4 = (const float4*)(xq + (size_t)row * KEYD);
    float4 qv[6];
    #pragma unroll
    for (int i = 0; i < 6; i++) qv[i] = q4[lane + 32 * i];
    float iq = g_invq[row];
    #pragma unroll
    for (int cc = 0; cc < 2; cc++) {
        int ci = w * 2 + cc;
        int p  = s_cand[ci];
        const float4* k4 = (const float4*)(ek + (size_t)p * KEYD);
        float s = 0.f;
        #pragma unroll
        for (int i = 0; i < 6; i++) {
            float4 kv = k4[lane + 32 * i];
            s += qv[i].x * kv.x + qv[i].y * kv.y + qv[i].z * kv.z + qv[i].w * kv.w;
        }
        #pragma unroll
        for (int off = 16; off; off >>= 1) s += __shfl_xor_sync(0xffffffffu, s, off);
        if (lane == 0) s_ex[ci] = 1.0f - s * iq * g_invk[p];
    }
    __syncthreads();

    if (t == 0) {
        bool used[TOP8];
        #pragma unroll
        for (int c = 0; c < TOP8; c++) used[c] = false;
        #pragma unroll
        for (int k = 0; k < TOPK; k++) {
            float best = INFINITY; int bi = 0x7fffffff; int slot = 0;
            #pragma unroll
            for (int c = 0; c < TOP8; c++) {
                if (!used[c] && (s_ex[c] < best || (s_ex[c] == best && s_cand[c] < bi))) {
                    best = s_ex[c]; bi = s_cand[c]; slot = c;
                }
            }
            used[slot] = true;
            g_idx[row * TOPK + k] = bi;
            atomicAdd(&g_cnt[bi], 1);
        }
    }
}

// column-sum partials of C: grid (4, 32), 128 threads; each block 128 cols x 64 rows
__global__ __launch_bounds__(128) void colpart_kernel(const float* __restrict__ C) {
    int col = blockIdx.x * 128 + threadIdx.x;
    int r0  = blockIdx.y * 64;
    float s = 0.f;
    #pragma unroll 4
    for (int r = 0; r < 64; r++) s += C[(size_t)(r0 + r) * POOL + col];
    g_partial[blockIdx.y * POOL + col] = s;
}

__global__ __launch_bounds__(512) void finish_kernel(float* __restrict__ out_loss,
                                                     float* __restrict__ out_counts) {
    int p = threadIdx.x;
    float colc = 0.f;
    #pragma unroll
    for (int g = 0; g < 32; g++) colc += g_partial[g * POOL + p];
    int c = g_cnt[p];
    out_counts[p] = (float)c;
    __shared__ float sm[512];
    sm[p] = colc * (float)c;
    __syncthreads();
    for (int s = 256; s > 0; s >>= 1) {
        if (p < s) sm[p] += sm[p + s];
        __syncthreads();
    }
    if (p == 0)
        *out_loss = 1.0f - sm[0] / ((float)B_ * (float)B_ * (float)TOPK);
}

// gather/concat Pk/Pv + x_block passthrough (r==20, scalar stores: XB_OFF unaligned)
__global__ __launch_bounds__(192) void gather_kernel(const float* __restrict__ e_p,
                                                     const float* __restrict__ g_p,
                                                     const float* __restrict__ xb,
                                                     float* __restrict__ out) {
    int b = blockIdx.y;
    int r = blockIdx.x;
    int t = threadIdx.x;
    if (r == 20) {
        float4 v = ((const float4*)(xb + (size_t)b * EMB))[t];
        float* d = out + XB_OFF + (size_t)b * EMB + 4 * t;
        d[0] = v.x; d[1] = v.y; d[2] = v.z; d[3] = v.w;
        return;
    }
    const float *sk, *sv;
    if (r < 16) {
        int p  = g_idx[b * TOPK + (r >> 2)];
        int rr = r & 3;
        sk = e_p + ((size_t)p * EPL + rr) * EMB;
        sv = e_p + ((size_t)p * EPL + 4 + rr) * EMB;
    } else {
        sk = g_p + (size_t)(r - 16) * EMB;
        sv = g_p + (size_t)(r - 16 + 4) * EMB;
    }
    size_t o = ((size_t)b * PK_ROWS + r) * EMB;
    float4 vk = ((const float4*)sk)[t];
    float4 vv = ((const float4*)sv)[t];
    ((float4*)(out + o))[t] = vk;
    ((float4*)(out + PV_OFF + o))[t] = vv;
}

// ---------------- launch ----------------
extern "C" void kernel_launch(void* const* d_in, const int* in_sizes, int n_in,
                              void* d_out, int out_size) {
    const float* x_querry = (const float*)d_in[0];
    const float* x_block  = (const float*)d_in[1];
    const float* e_k      = (const float*)d_in[2];
    const float* e_p      = (const float*)d_in[3];
    const float* g_p      = (const float*)d_in[4];
    (void)in_sizes; (void)n_in; (void)out_size;

    float* out = (float*)d_out;
    float* d_C = nullptr;
    cudaGetSymbolAddress((void**)&d_C, g_C);

    zero_kernel<<<1, POOL>>>();                                   // launch 1
    invnorm_q_kernel<<<B_ / 8, 256>>>(x_querry);                  // launch 2
    invnorm_k_kernel<<<POOL / 8, 256>>>(e_k);                     // launch 3
    gemm_tf32_kernel<<<dim3(POOL / BN, B_ / BM), 256>>>(x_querry, e_k, d_C);  // launch 4 (profiled)
    route_kernel<<<B_, 128>>>(d_C, x_querry, e_k);
    colpart_kernel<<<dim3(4, 32), 128>>>(d_C);
    finish_kernel<<<1, 512>>>(out + LOSS_OFF, out + CNT_OFF);
    gather_kernel<<<dim3(PK_ROWS + 1, B_), 192>>>(e_p, g_p, x_block, out);
}

// round 6
// speedup vs baseline: 1.2415x; 1.2415x over previous
#include <cuda_runtime.h>
#include <cstdint>
#include <math.h>

// ---------------- problem constants ----------------
#define B_    2048
#define POOL  512
#define TOPK  4
#define TOP8  8
#define EPL   8
#define GPL   8
#define EMB   768
#define KEYD  768

// output offsets (float32 elements)
#define PK_ROWS   20
#define PK_SZ     ((size_t)B_ * PK_ROWS * EMB)
#define PV_OFF    (PK_SZ)
#define LOSS_OFF  (2 * PK_SZ)
#define CNT_OFF   (LOSS_OFF + 1)
#define XB_OFF    (CNT_OFF + POOL)   // odd offset -> only 4-byte aligned!

// ---------------- device scratch ----------------
__device__ float g_C[B_ * POOL];
__device__ float g_invq[B_];
__device__ float g_invk[POOL];
__device__ float g_colsum[POOL];
__device__ int   g_idx[B_ * TOPK];
__device__ int   g_cnt[POOL];

// ---------------- helpers ----------------
__device__ __forceinline__ void mma_tf32(float* c, const uint32_t* a, const uint32_t* b) {
    asm volatile(
        "mma.sync.aligned.m16n8k8.row.col.f32.tf32.tf32.f32 "
        "{%0,%1,%2,%3}, {%4,%5,%6,%7}, {%8,%9}, {%0,%1,%2,%3};"
        : "+f"(c[0]), "+f"(c[1]), "+f"(c[2]), "+f"(c[3])
        : "r"(a[0]), "r"(a[1]), "r"(a[2]), "r"(a[3]), "r"(b[0]), "r"(b[1]));
}
__device__ __forceinline__ void cpa16(uint32_t dst, const void* src) {
    asm volatile("cp.async.cg.shared.global [%0], [%1], 16;" :: "r"(dst), "l"(src));
}
__device__ __forceinline__ float row_invnorm(const float4* s4, int lane) {
    float ss = 0.f;
    #pragma unroll
    for (int i = 0; i < 6; i++) {
        float4 v = s4[lane + 32 * i];
        ss += v.x * v.x + v.y * v.y + v.z * v.z + v.w * v.w;
    }
    #pragma unroll
    for (int off = 16; off; off >>= 1) ss += __shfl_xor_sync(0xffffffffu, ss, off);
    return 1.0f / fmaxf(sqrtf(ss), 1e-12f);
}

// ---------------- kernel 1: prep (zero + both invnorms) ----------------
__global__ __launch_bounds__(256) void prep_kernel(const float* __restrict__ xq,
                                                   const float* __restrict__ ek) {
    if (blockIdx.x == 0) {
        int t = threadIdx.x;
        g_cnt[t] = 0; g_cnt[t + 256] = 0;
        g_colsum[t] = 0.f; g_colsum[t + 256] = 0.f;
    }
    int warp = (blockIdx.x * 256 + threadIdx.x) >> 5;
    int lane = threadIdx.x & 31;
    if (warp < B_) {
        float inv = row_invnorm((const float4*)(xq + (size_t)warp * KEYD), lane);
        if (lane == 0) g_invq[warp] = inv;
    } else if (warp < B_ + POOL) {
        int r = warp - B_;
        float inv = row_invnorm((const float4*)(ek + (size_t)r * KEYD), lane);
        if (lane == 0) g_invk[r] = inv;
    }
}

// ---------------- kernel 2: tf32 GEMM (cp.async, no cvt) + colsum epilogue ----
// C[B_,POOL] = (xq * eK^T) * invq[m] * invk[n];  g_colsum[n] += sum_m C[m][n]
// BM=BN=64, BK=32, 128 threads (4 warps, 2x2, warp tile 32x32), 2-stage cp.async
#define BM 64
#define BN 64
#define BK 32
#define RST 36                      // row stride (words): bank = (4*row + k) & 31
#define STAGE_B (64 * RST * 4)      // 9216 bytes per stage per matrix
__global__ __launch_bounds__(128) void gemm_tf32_kernel(const float* __restrict__ A,
                                                        const float* __restrict__ Bm,
                                                        float* __restrict__ C) {
    __shared__ __align__(16) uint32_t As[2][BM][RST];
    __shared__ __align__(16) uint32_t Bs[2][BN][RST];

    const int t    = threadIdx.x;
    const int lane = t & 31;
    const int wid  = t >> 5;
    const int gid  = lane >> 2;
    const int tig  = lane & 3;
    const int wm   = (wid >> 1) * 32;
    const int wn   = (wid & 1) * 32;
    const int m0   = blockIdx.y * BM;
    const int n0   = blockIdx.x * BN;

    // load mapping: 2 threads per row, 16 consecutive floats each
    const int arow = t >> 1;
    const int half = t & 1;
    const float* Aptr = A  + (size_t)(m0 + arow) * KEYD + half * 16;
    const float* Bptr = Bm + (size_t)(n0 + arow) * KEYD + half * 16;
    const uint32_t sA = (uint32_t)__cvta_generic_to_shared(&As[0][arow][half * 16]);
    const uint32_t sB = (uint32_t)__cvta_generic_to_shared(&Bs[0][arow][half * 16]);

    #define ISSUE(st_, k0_)                                         \
        { _Pragma("unroll")                                         \
          for (int i = 0; i < 4; i++) {                             \
              cpa16(sA + (st_) * STAGE_B + i * 16, Aptr + (k0_) + i * 4); \
              cpa16(sB + (st_) * STAGE_B + i * 16, Bptr + (k0_) + i * 4); \
          }                                                         \
          asm volatile("cp.async.commit_group;"); }

    float acc[2][4][4];
    #pragma unroll
    for (int i = 0; i < 2; i++)
        #pragma unroll
        for (int j = 0; j < 4; j++)
            #pragma unroll
            for (int v = 0; v < 4; v++) acc[i][j][v] = 0.f;

    ISSUE(0, 0);

    const int NIT = KEYD / BK;   // 24
    for (int it = 0; it < NIT; it++) {
        asm volatile("cp.async.wait_group 0;");
        __syncthreads();
        if (it + 1 < NIT) ISSUE((it + 1) & 1, (it + 1) * BK);
        const int st = it & 1;
        #pragma unroll
        for (int kk = 0; kk < BK; kk += 8) {
            uint32_t af[2][4], bf[4][2];
            #pragma unroll
            for (int mt = 0; mt < 2; mt++) {
                int mb = wm + mt * 16 + gid;
                af[mt][0] = As[st][mb][kk + tig];
                af[mt][1] = As[st][mb + 8][kk + tig];
                af[mt][2] = As[st][mb][kk + tig + 4];
                af[mt][3] = As[st][mb + 8][kk + tig + 4];
            }
            #pragma unroll
            for (int nt = 0; nt < 4; nt++) {
                int nb = wn + nt * 8 + gid;
                bf[nt][0] = Bs[st][nb][kk + tig];
                bf[nt][1] = Bs[st][nb][kk + tig + 4];
            }
            #pragma unroll
            for (int mt = 0; mt < 2; mt++)
                #pragma unroll
                for (int nt = 0; nt < 4; nt++)
                    mma_tf32(acc[mt][nt], af[mt], bf[nt]);
        }
        __syncthreads();
    }

    // epilogue: scale, store C, accumulate column sums
    float cs0[4] = {0.f, 0.f, 0.f, 0.f};
    float cs1[4] = {0.f, 0.f, 0.f, 0.f};
    #pragma unroll
    for (int mt = 0; mt < 2; mt++) {
        int m = m0 + wm + mt * 16 + gid;
        float iq0 = g_invq[m], iq1 = g_invq[m + 8];
        #pragma unroll
        for (int nt = 0; nt < 4; nt++) {
            int n = n0 + wn + nt * 8 + 2 * tig;
            float ik0 = g_invk[n], ik1 = g_invk[n + 1];
            float v0 = acc[mt][nt][0] * iq0 * ik0;
            float v1 = acc[mt][nt][1] * iq0 * ik1;
            float v2 = acc[mt][nt][2] * iq1 * ik0;
            float v3 = acc[mt][nt][3] * iq1 * ik1;
            C[(size_t)m * POOL + n]           = v0;
            C[(size_t)m * POOL + n + 1]       = v1;
            C[(size_t)(m + 8) * POOL + n]     = v2;
            C[(size_t)(m + 8) * POOL + n + 1] = v3;
            cs0[nt] += v0 + v2;
            cs1[nt] += v1 + v3;
        }
    }
    #pragma unroll
    for (int nt = 0; nt < 4; nt++) {
        float c0 = cs0[nt], c1 = cs1[nt];
        #pragma unroll
        for (int off = 4; off < 32; off <<= 1) {
            c0 += __shfl_xor_sync(0xffffffffu, c0, off);
            c1 += __shfl_xor_sync(0xffffffffu, c1, off);
        }
        if (gid == 0) {
            int n = n0 + wn + nt * 8 + 2 * tig;
            atomicAdd(&g_colsum[n], c0);
            atomicAdd(&g_colsum[n + 1], c1);
        }
    }
}

// ---------------- kernel 3: route (approx top-8 + exact fp32 recheck) --------
__global__ __launch_bounds__(128) void route_kernel(const float* __restrict__ C,
                                                    const float* __restrict__ xq,
                                                    const float* __restrict__ ek) {
    int row  = blockIdx.x;
    int t    = threadIdx.x;
    int lane = t & 31;
    int w    = t >> 5;
    __shared__ int   s_cand[TOP8];
    __shared__ float s_ex[TOP8];

    if (w == 0) {
        const float* crow = C + (size_t)row * POOL;
        float d[16];
        #pragma unroll
        for (int u = 0; u < 16; u++) d[u] = 1.0f - crow[u * 32 + lane];
        #pragma unroll
        for (int k = 0; k < TOP8; k++) {
            float best = INFINITY; int bi = 0x7fffffff;
            #pragma unroll
            for (int u = 0; u < 16; u++) {
                int p = u * 32 + lane;
                if (d[u] < best || (d[u] == best && p < bi)) { best = d[u]; bi = p; }
            }
            #pragma unroll
            for (int off = 16; off; off >>= 1) {
                float ov = __shfl_xor_sync(0xffffffffu, best, off);
                int   oi = __shfl_xor_sync(0xffffffffu, bi, off);
                if (ov < best || (ov == best && oi < bi)) { best = ov; bi = oi; }
            }
            if (lane == 0) s_cand[k] = bi;
            int ul = bi >> 5, ll = bi & 31;
            #pragma unroll
            for (int u = 0; u < 16; u++)
                if (u == ul && ll == lane) d[u] = INFINITY;
        }
    }
    __syncthreads();

    const float4* q4 = (const float4*)(xq + (size_t)row * KEYD);
    float4 qv[6];
    #pragma unroll
    for (int i = 0; i < 6; i++) qv[i] = q4[lane + 32 * i];
    float iq = g_invq[row];
    #pragma unroll
    for (int cc = 0; cc < 2; cc++) {
        int ci = w * 2 + cc;
        int p  = s_cand[ci];
        const float4* k4 = (const float4*)(ek + (size_t)p * KEYD);
        float s = 0.f;
        #pragma unroll
        for (int i = 0; i < 6; i++) {
            float4 kv = k4[lane + 32 * i];
            s += qv[i].x * kv.x + qv[i].y * kv.y + qv[i].z * kv.z + qv[i].w * kv.w;
        }
        #pragma unroll
        for (int off = 16; off; off >>= 1) s += __shfl_xor_sync(0xffffffffu, s, off);
        if (lane == 0) s_ex[ci] = 1.0f - s * iq * g_invk[p];
    }
    __syncthreads();

    if (t == 0) {
        bool used[TOP8];
        #pragma unroll
        for (int c = 0; c < TOP8; c++) used[c] = false;
        #pragma unroll
        for (int k = 0; k < TOPK; k++) {
            float best = INFINITY; int bi = 0x7fffffff; int slot = 0;
            #pragma unroll
            for (int c = 0; c < TOP8; c++) {
                if (!used[c] && (s_ex[c] < best || (s_ex[c] == best && s_cand[c] < bi))) {
                    best = s_ex[c]; bi = s_cand[c]; slot = c;
                }
            }
            used[slot] = true;
            g_idx[row * TOPK + k] = bi;
            atomicAdd(&g_cnt[bi], 1);
        }
    }
}

// ---------------- kernel 4: gather/concat + passthrough + loss/counts --------
__global__ __launch_bounds__(192) void gather_kernel(const float* __restrict__ e_p,
                                                     const float* __restrict__ g_p,
                                                     const float* __restrict__ xb,
                                                     float* __restrict__ out) {
    int b = blockIdx.y;
    int r = blockIdx.x;
    int t = threadIdx.x;
    if (r == 20) {
        // x_block passthrough (unaligned dst -> scalar stores)
        float4 v = ((const float4*)(xb + (size_t)b * EMB))[t];
        float* d = out + XB_OFF + (size_t)b * EMB + 4 * t;
        d[0] = v.x; d[1] = v.y; d[2] = v.z; d[3] = v.w;
        if (b == 0) {
            // loss + counts (runs after route/gemm complete)
            __shared__ float s_w[6];
            float local = 0.f;
            #pragma unroll
            for (int rep = 0; rep < 3; rep++) {
                int p = t + rep * 192;
                if (p < POOL) {
                    int c = g_cnt[p];
                    out[CNT_OFF + p] = (float)c;
                    local += g_colsum[p] * (float)c;
                }
            }
            #pragma unroll
            for (int off = 16; off; off >>= 1)
                local += __shfl_xor_sync(0xffffffffu, local, off);
            if ((t & 31) == 0) s_w[t >> 5] = local;
            __syncthreads();
            if (t == 0) {
                float tot = 0.f;
                #pragma unroll
                for (int i = 0; i < 6; i++) tot += s_w[i];
                out[LOSS_OFF] = 1.0f - tot / ((float)B_ * (float)B_ * (float)TOPK);
            }
        }
        return;
    }
    const float *sk, *sv;
    if (r < 16) {
        int p  = g_idx[b * TOPK + (r >> 2)];
        int rr = r & 3;
        sk = e_p + ((size_t)p * EPL + rr) * EMB;
        sv = e_p + ((size_t)p * EPL + 4 + rr) * EMB;
    } else {
        sk = g_p + (size_t)(r - 16) * EMB;
        sv = g_p + (size_t)(r - 16 + 4) * EMB;
    }
    size_t o = ((size_t)b * PK_ROWS + r) * EMB;
    float4 vk = ((const float4*)sk)[t];
    float4 vv = ((const float4*)sv)[t];
    ((float4*)(out + o))[t] = vk;
    ((float4*)(out + PV_OFF + o))[t] = vv;
}

// ---------------- launch ----------------
extern "C" void kernel_launch(void* const* d_in, const int* in_sizes, int n_in,
                              void* d_out, int out_size) {
    const float* x_querry = (const float*)d_in[0];
    const float* x_block  = (const float*)d_in[1];
    const float* e_k      = (const float*)d_in[2];
    const float* e_p      = (const float*)d_in[3];
    const float* g_p      = (const float*)d_in[4];
    (void)in_sizes; (void)n_in; (void)out_size;

    float* out = (float*)d_out;
    float* d_C = nullptr;
    cudaGetSymbolAddress((void**)&d_C, g_C);

    prep_kernel<<<(B_ + POOL) / 8, 256>>>(x_querry, e_k);                    // 1
    gemm_tf32_kernel<<<dim3(POOL / BN, B_ / BM), 128>>>(x_querry, e_k, d_C); // 2
    route_kernel<<<B_, 128>>>(d_C, x_querry, e_k);                           // 3
    gather_kernel<<<dim3(PK_ROWS + 1, B_), 192>>>(e_p, g_p, x_block, out);   // 4 (profiled)
}

// round 7
// speedup vs baseline: 1.3008x; 1.0478x over previous
#include <cuda_runtime.h>
#include <cstdint>
#include <math.h>

// ---------------- problem constants ----------------
#define B_    2048
#define POOL  512
#define TOPK  4
#define TOP8  8
#define EPL   8
#define GPL   8
#define EMB   768
#define KEYD  768

// output offsets (float32 elements)
#define PK_ROWS   20
#define PK_SZ     ((size_t)B_ * PK_ROWS * EMB)
#define PV_OFF    (PK_SZ)
#define LOSS_OFF  (2 * PK_SZ)
#define CNT_OFF   (LOSS_OFF + 1)
#define XB_OFF    (CNT_OFF + POOL)   // odd offset -> only 4-byte aligned!

// ---------------- device scratch ----------------
__device__ float g_C[B_ * POOL];
__device__ float g_invq[B_];
__device__ float g_invk[POOL];
__device__ float g_colsum[POOL];
__device__ int   g_idx[B_ * TOPK];
__device__ int   g_cnt[POOL];

// ---------------- helpers ----------------
__device__ __forceinline__ void mma_tf32(float* c, const uint32_t* a, const uint32_t* b) {
    asm volatile(
        "mma.sync.aligned.m16n8k8.row.col.f32.tf32.tf32.f32 "
        "{%0,%1,%2,%3}, {%4,%5,%6,%7}, {%8,%9}, {%0,%1,%2,%3};"
        : "+f"(c[0]), "+f"(c[1]), "+f"(c[2]), "+f"(c[3])
        : "r"(a[0]), "r"(a[1]), "r"(a[2]), "r"(a[3]), "r"(b[0]), "r"(b[1]));
}
__device__ __forceinline__ void cpa16(uint32_t dst, const void* src) {
    asm volatile("cp.async.cg.shared.global [%0], [%1], 16;" :: "r"(dst), "l"(src));
}
__device__ __forceinline__ float row_invnorm(const float4* s4, int lane) {
    float ss = 0.f;
    #pragma unroll
    for (int i = 0; i < 6; i++) {
        float4 v = s4[lane + 32 * i];
        ss += v.x * v.x + v.y * v.y + v.z * v.z + v.w * v.w;
    }
    #pragma unroll
    for (int off = 16; off; off >>= 1) ss += __shfl_xor_sync(0xffffffffu, ss, off);
    return 1.0f / fmaxf(sqrtf(ss), 1e-12f);
}

// ---------------- kernel 1: prep (zero + both invnorms) ----------------
__global__ __launch_bounds__(256) void prep_kernel(const float* __restrict__ xq,
                                                   const float* __restrict__ ek) {
    if (blockIdx.x == 0) {
        int t = threadIdx.x;
        g_cnt[t] = 0; g_cnt[t + 256] = 0;
        g_colsum[t] = 0.f; g_colsum[t + 256] = 0.f;
    }
    int warp = (blockIdx.x * 256 + threadIdx.x) >> 5;
    int lane = threadIdx.x & 31;
    if (warp < B_) {
        float inv = row_invnorm((const float4*)(xq + (size_t)warp * KEYD), lane);
        if (lane == 0) g_invq[warp] = inv;
    } else if (warp < B_ + POOL) {
        int r = warp - B_;
        float inv = row_invnorm((const float4*)(ek + (size_t)r * KEYD), lane);
        if (lane == 0) g_invk[r] = inv;
    }
}

// ---------------- kernel 2: tf32 GEMM (cp.async, no cvt) + colsum epilogue ----
#define BM 64
#define BN 64
#define BK 32
#define RST 36
#define STAGE_B (64 * RST * 4)
__global__ __launch_bounds__(128) void gemm_tf32_kernel(const float* __restrict__ A,
                                                        const float* __restrict__ Bm,
                                                        float* __restrict__ C) {
    __shared__ __align__(16) uint32_t As[2][BM][RST];
    __shared__ __align__(16) uint32_t Bs[2][BN][RST];

    const int t    = threadIdx.x;
    const int lane = t & 31;
    const int wid  = t >> 5;
    const int gid  = lane >> 2;
    const int tig  = lane & 3;
    const int wm   = (wid >> 1) * 32;
    const int wn   = (wid & 1) * 32;
    const int m0   = blockIdx.y * BM;
    const int n0   = blockIdx.x * BN;

    const int arow = t >> 1;
    const int half = t & 1;
    const float* Aptr = A  + (size_t)(m0 + arow) * KEYD + half * 16;
    const float* Bptr = Bm + (size_t)(n0 + arow) * KEYD + half * 16;
    const uint32_t sA = (uint32_t)__cvta_generic_to_shared(&As[0][arow][half * 16]);
    const uint32_t sB = (uint32_t)__cvta_generic_to_shared(&Bs[0][arow][half * 16]);

    #define ISSUE(st_, k0_)                                         \
        { _Pragma("unroll")                                         \
          for (int i = 0; i < 4; i++) {                             \
              cpa16(sA + (st_) * STAGE_B + i * 16, Aptr + (k0_) + i * 4); \
              cpa16(sB + (st_) * STAGE_B + i * 16, Bptr + (k0_) + i * 4); \
          }                                                         \
          asm volatile("cp.async.commit_group;"); }

    float acc[2][4][4];
    #pragma unroll
    for (int i = 0; i < 2; i++)
        #pragma unroll
        for (int j = 0; j < 4; j++)
            #pragma unroll
            for (int v = 0; v < 4; v++) acc[i][j][v] = 0.f;

    ISSUE(0, 0);

    const int NIT = KEYD / BK;   // 24
    for (int it = 0; it < NIT; it++) {
        asm volatile("cp.async.wait_group 0;");
        __syncthreads();
        if (it + 1 < NIT) ISSUE((it + 1) & 1, (it + 1) * BK);
        const int st = it & 1;
        #pragma unroll
        for (int kk = 0; kk < BK; kk += 8) {
            uint32_t af[2][4], bf[4][2];
            #pragma unroll
            for (int mt = 0; mt < 2; mt++) {
                int mb = wm + mt * 16 + gid;
                af[mt][0] = As[st][mb][kk + tig];
                af[mt][1] = As[st][mb + 8][kk + tig];
                af[mt][2] = As[st][mb][kk + tig + 4];
                af[mt][3] = As[st][mb + 8][kk + tig + 4];
            }
            #pragma unroll
            for (int nt = 0; nt < 4; nt++) {
                int nb = wn + nt * 8 + gid;
                bf[nt][0] = Bs[st][nb][kk + tig];
                bf[nt][1] = Bs[st][nb][kk + tig + 4];
            }
            #pragma unroll
            for (int mt = 0; mt < 2; mt++)
                #pragma unroll
                for (int nt = 0; nt < 4; nt++)
                    mma_tf32(acc[mt][nt], af[mt], bf[nt]);
        }
        __syncthreads();
    }

    float cs0[4] = {0.f, 0.f, 0.f, 0.f};
    float cs1[4] = {0.f, 0.f, 0.f, 0.f};
    #pragma unroll
    for (int mt = 0; mt < 2; mt++) {
        int m = m0 + wm + mt * 16 + gid;
        float iq0 = g_invq[m], iq1 = g_invq[m + 8];
        #pragma unroll
        for (int nt = 0; nt < 4; nt++) {
            int n = n0 + wn + nt * 8 + 2 * tig;
            float ik0 = g_invk[n], ik1 = g_invk[n + 1];
            float v0 = acc[mt][nt][0] * iq0 * ik0;
            float v1 = acc[mt][nt][1] * iq0 * ik1;
            float v2 = acc[mt][nt][2] * iq1 * ik0;
            float v3 = acc[mt][nt][3] * iq1 * ik1;
            C[(size_t)m * POOL + n]           = v0;
            C[(size_t)m * POOL + n + 1]       = v1;
            C[(size_t)(m + 8) * POOL + n]     = v2;
            C[(size_t)(m + 8) * POOL + n + 1] = v3;
            cs0[nt] += v0 + v2;
            cs1[nt] += v1 + v3;
        }
    }
    #pragma unroll
    for (int nt = 0; nt < 4; nt++) {
        float c0 = cs0[nt], c1 = cs1[nt];
        #pragma unroll
        for (int off = 4; off < 32; off <<= 1) {
            c0 += __shfl_xor_sync(0xffffffffu, c0, off);
            c1 += __shfl_xor_sync(0xffffffffu, c1, off);
        }
        if (gid == 0) {
            int n = n0 + wn + nt * 8 + 2 * tig;
            atomicAdd(&g_colsum[n], c0);
            atomicAdd(&g_colsum[n + 1], c1);
        }
    }
}

// ---------------- kernel 3: route (approx top-8 + exact fp32 recheck) --------
__global__ __launch_bounds__(128) void route_kernel(const float* __restrict__ C,
                                                    const float* __restrict__ xq,
                                                    const float* __restrict__ ek) {
    int row  = blockIdx.x;
    int t    = threadIdx.x;
    int lane = t & 31;
    int w    = t >> 5;
    __shared__ int   s_cand[TOP8];
    __shared__ float s_ex[TOP8];

    if (w == 0) {
        const float* crow = C + (size_t)row * POOL;
        float d[16];
        #pragma unroll
        for (int u = 0; u < 16; u++) d[u] = 1.0f - crow[u * 32 + lane];
        #pragma unroll
        for (int k = 0; k < TOP8; k++) {
            float best = INFINITY; int bi = 0x7fffffff;
            #pragma unroll
            for (int u = 0; u < 16; u++) {
                int p = u * 32 + lane;
                if (d[u] < best || (d[u] == best && p < bi)) { best = d[u]; bi = p; }
            }
            #pragma unroll
            for (int off = 16; off; off >>= 1) {
                float ov = __shfl_xor_sync(0xffffffffu, best, off);
                int   oi = __shfl_xor_sync(0xffffffffu, bi, off);
                if (ov < best || (ov == best && oi < bi)) { best = ov; bi = oi; }
            }
            if (lane == 0) s_cand[k] = bi;
            int ul = bi >> 5, ll = bi & 31;
            #pragma unroll
            for (int u = 0; u < 16; u++)
                if (u == ul && ll == lane) d[u] = INFINITY;
        }
    }
    __syncthreads();

    const float4* q4 = (const float4*)(xq + (size_t)row * KEYD);
    float4 qv[6];
    #pragma unroll
    for (int i = 0; i < 6; i++) qv[i] = q4[lane + 32 * i];
    float iq = g_invq[row];
    #pragma unroll
    for (int cc = 0; cc < 2; cc++) {
        int ci = w * 2 + cc;
        int p  = s_cand[ci];
        const float4* k4 = (const float4*)(ek + (size_t)p * KEYD);
        float s = 0.f;
        #pragma unroll
        for (int i = 0; i < 6; i++) {
            float4 kv = k4[lane + 32 * i];
            s += qv[i].x * kv.x + qv[i].y * kv.y + qv[i].z * kv.z + qv[i].w * kv.w;
        }
        #pragma unroll
        for (int off = 16; off; off >>= 1) s += __shfl_xor_sync(0xffffffffu, s, off);
        if (lane == 0) s_ex[ci] = 1.0f - s * iq * g_invk[p];
    }
    __syncthreads();

    if (t == 0) {
        bool used[TOP8];
        #pragma unroll
        for (int c = 0; c < TOP8; c++) used[c] = false;
        #pragma unroll
        for (int k = 0; k < TOPK; k++) {
            float best = INFINITY; int bi = 0x7fffffff; int slot = 0;
            #pragma unroll
            for (int c = 0; c < TOP8; c++) {
                if (!used[c] && (s_ex[c] < best || (s_ex[c] == best && s_cand[c] < bi))) {
                    best = s_ex[c]; bi = s_cand[c]; slot = c;
                }
            }
            used[slot] = true;
            g_idx[row * TOPK + k] = bi;
            atomicAdd(&g_cnt[bi], 1);
        }
    }
}

// ---------------- kernel 4: gather/concat + passthrough + loss/counts --------
// grid (B_, 5), 256 threads. k<4: one selected pool entry -> 8 rows (4 Ek + 4 Ev),
// warp-per-row, 6 float4 streaming stores per thread. k==4: static G rows + x_block.
__global__ __launch_bounds__(256) void gather_kernel(const float* __restrict__ e_p,
                                                     const float* __restrict__ g_p,
                                                     const float* __restrict__ xb,
                                                     float* __restrict__ out) {
    const int b = blockIdx.x;
    const int k = blockIdx.y;
    const int t = threadIdx.x;
    const int g = t >> 5;        // warp = source row 0..7
    const int lane = t & 31;

    if (k < 4) {
        int p = g_idx[b * TOPK + k];
        const float4* src = (const float4*)(e_p + ((size_t)p * EPL + g) * EMB);
        float4* dst = (g < 4)
            ? (float4*)(out + ((size_t)b * PK_ROWS + k * 4 + g) * EMB)
            : (float4*)(out + PV_OFF + ((size_t)b * PK_ROWS + k * 4 + (g - 4)) * EMB);
        #pragma unroll
        for (int i = 0; i < 6; i++)
            __stcs(dst + lane + 32 * i, src[lane + 32 * i]);
        return;
    }

    // k == 4 : static rows.  Gk = g_p[0:4] -> Pk rows 16..19 ; Gv = g_p[4:8] -> Pv rows 16..19
    {
        const float4* src = (const float4*)(g_p + (size_t)g * EMB);
        float4* dst = (g < 4)
            ? (float4*)(out + ((size_t)b * PK_ROWS + 16 + g) * EMB)
            : (float4*)(out + PV_OFF + ((size_t)b * PK_ROWS + 16 + (g - 4)) * EMB);
        #pragma unroll
        for (int i = 0; i < 6; i++)
            __stcs(dst + lane + 32 * i, src[lane + 32 * i]);
    }
    // x_block passthrough (dst only 4B-aligned -> scalar stores, coalesced)
    {
        const float* s = xb + (size_t)b * EMB;
        float* d = out + XB_OFF + (size_t)b * EMB;
        #pragma unroll
        for (int i = 0; i < 3; i++)
            __stcs(d + t + 256 * i, s[t + 256 * i]);
    }
    // loss + counts, one block only
    if (b == 0) {
        __shared__ float s_w[8];
        float local = 0.f;
        #pragma unroll
        for (int rep = 0; rep < 2; rep++) {
            int p = t + rep * 256;
            int c = g_cnt[p];
            out[CNT_OFF + p] = (float)c;
            local += g_colsum[p] * (float)c;
        }
        #pragma unroll
        for (int off = 16; off; off >>= 1)
            local += __shfl_xor_sync(0xffffffffu, local, off);
        if (lane == 0) s_w[g] = local;
        __syncthreads();
        if (t == 0) {
            float tot = 0.f;
            #pragma unroll
            for (int i = 0; i < 8; i++) tot += s_w[i];
            out[LOSS_OFF] = 1.0f - tot / ((float)B_ * (float)B_ * (float)TOPK);
        }
    }
}

// ---------------- launch ----------------
extern "C" void kernel_launch(void* const* d_in, const int* in_sizes, int n_in,
                              void* d_out, int out_size) {
    const float* x_querry = (const float*)d_in[0];
    const float* x_block  = (const float*)d_in[1];
    const float* e_k      = (const float*)d_in[2];
    const float* e_p      = (const float*)d_in[3];
    const float* g_p      = (const float*)d_in[4];
    (void)in_sizes; (void)n_in; (void)out_size;

    float* out = (float*)d_out;
    float* d_C = nullptr;
    cudaGetSymbolAddress((void**)&d_C, g_C);

    prep_kernel<<<(B_ + POOL) / 8, 256>>>(x_querry, e_k);                    // 1
    gemm_tf32_kernel<<<dim3(POOL / BN, B_ / BM), 128>>>(x_querry, e_k, d_C); // 2
    route_kernel<<<B_, 128>>>(d_C, x_querry, e_k);                           // 3
    gather_kernel<<<dim3(B_, 5), 256>>>(e_p, g_p, x_block, out);             // 4 (profiled)
}

// round 8
// speedup vs baseline: 1.3818x; 1.0623x over previous
#include <cuda_runtime.h>
#include <cstdint>
#include <math.h>

// ---------------- problem constants ----------------
#define B_    2048
#define POOL  512
#define TOPK  4
#define TOP8  8
#define EPL   8
#define GPL   8
#define EMB   768
#define KEYD  768

// output offsets (float32 elements)
#define PK_ROWS   20
#define PK_SZ     ((size_t)B_ * PK_ROWS * EMB)
#define PV_OFF    (PK_SZ)
#define LOSS_OFF  (2 * PK_SZ)
#define CNT_OFF   (LOSS_OFF + 1)
#define XB_OFF    (CNT_OFF + POOL)   // odd offset -> only 4-byte aligned!

// ---------------- device scratch ----------------
__device__ float g_C[B_ * POOL];
__device__ float g_invq[B_];
__device__ float g_invk[POOL];
__device__ float g_colsum[POOL];
__device__ int   g_cnt[POOL];

// ---------------- helpers ----------------
__device__ __forceinline__ void mma_tf32(float* c, const uint32_t* a, const uint32_t* b) {
    asm volatile(
        "mma.sync.aligned.m16n8k8.row.col.f32.tf32.tf32.f32 "
        "{%0,%1,%2,%3}, {%4,%5,%6,%7}, {%8,%9}, {%0,%1,%2,%3};"
        : "+f"(c[0]), "+f"(c[1]), "+f"(c[2]), "+f"(c[3])
        : "r"(a[0]), "r"(a[1]), "r"(a[2]), "r"(a[3]), "r"(b[0]), "r"(b[1]));
}
__device__ __forceinline__ void cpa16(uint32_t dst, const void* src) {
    asm volatile("cp.async.cg.shared.global [%0], [%1], 16;" :: "r"(dst), "l"(src));
}
__device__ __forceinline__ float row_invnorm(const float4* s4, int lane) {
    float ss = 0.f;
    #pragma unroll
    for (int i = 0; i < 6; i++) {
        float4 v = s4[lane + 32 * i];
        ss += v.x * v.x + v.y * v.y + v.z * v.z + v.w * v.w;
    }
    #pragma unroll
    for (int off = 16; off; off >>= 1) ss += __shfl_xor_sync(0xffffffffu, ss, off);
    return 1.0f / fmaxf(sqrtf(ss), 1e-12f);
}

// ---------------- kernel 1: prep (zero + both invnorms) ----------------
__global__ __launch_bounds__(256) void prep_kernel(const float* __restrict__ xq,
                                                   const float* __restrict__ ek) {
    if (blockIdx.x == 0) {
        int t = threadIdx.x;
        g_cnt[t] = 0; g_cnt[t + 256] = 0;
        g_colsum[t] = 0.f; g_colsum[t + 256] = 0.f;
    }
    int warp = (blockIdx.x * 256 + threadIdx.x) >> 5;
    int lane = threadIdx.x & 31;
    if (warp < B_) {
        float inv = row_invnorm((const float4*)(xq + (size_t)warp * KEYD), lane);
        if (lane == 0) g_invq[warp] = inv;
    } else if (warp < B_ + POOL) {
        int r = warp - B_;
        float inv = row_invnorm((const float4*)(ek + (size_t)r * KEYD), lane);
        if (lane == 0) g_invk[r] = inv;
    }
}

// ---------------- kernel 2: tf32 GEMM + colsum epilogue ----------------
// 256 threads, 8 warps as 4m x 2n (warp tile 16x32), BM=BN=64, BK=32, 2-stage cp.async
#define BM 64
#define BN 64
#define BK 32
#define RST 36
#define STAGE_B (64 * RST * 4)
__global__ __launch_bounds__(256) void gemm_tf32_kernel(const float* __restrict__ A,
                                                        const float* __restrict__ Bm,
                                                        float* __restrict__ C) {
    __shared__ __align__(16) uint32_t As[2][BM][RST];
    __shared__ __align__(16) uint32_t Bs[2][BN][RST];

    const int t    = threadIdx.x;
    const int lane = t & 31;
    const int wid  = t >> 5;
    const int gid  = lane >> 2;
    const int tig  = lane & 3;
    const int wm   = (wid >> 1) * 16;   // 4 warps in M: 0,16,32,48
    const int wn   = (wid & 1) * 32;    // 2 warps in N: 0,32
    const int m0   = blockIdx.y * BM;
    const int n0   = blockIdx.x * BN;

    // cp.async mapping: 4 threads per row, 8 floats (2 float4) each
    const int arow = t >> 2;            // 0..63
    const int aq   = (t & 3) * 8;       // word offset in row: 0,8,16,24
    const float* Aptr = A  + (size_t)(m0 + arow) * KEYD + aq;
    const float* Bptr = Bm + (size_t)(n0 + arow) * KEYD + aq;
    const uint32_t sA = (uint32_t)__cvta_generic_to_shared(&As[0][arow][aq]);
    const uint32_t sB = (uint32_t)__cvta_generic_to_shared(&Bs[0][arow][aq]);

    #define ISSUE(st_, k0_)                                               \
        { cpa16(sA + (st_) * STAGE_B,      Aptr + (k0_));                 \
          cpa16(sA + (st_) * STAGE_B + 16, Aptr + (k0_) + 4);             \
          cpa16(sB + (st_) * STAGE_B,      Bptr + (k0_));                 \
          cpa16(sB + (st_) * STAGE_B + 16, Bptr + (k0_) + 4);             \
          asm volatile("cp.async.commit_group;"); }

    float acc[4][4];   // 4 n-tiles of m16n8
    #pragma unroll
    for (int j = 0; j < 4; j++)
        #pragma unroll
        for (int v = 0; v < 4; v++) acc[j][v] = 0.f;

    ISSUE(0, 0);

    const int NIT = KEYD / BK;   // 24
    for (int it = 0; it < NIT; it++) {
        asm volatile("cp.async.wait_group 0;");
        __syncthreads();
        if (it + 1 < NIT) ISSUE((it + 1) & 1, (it + 1) * BK);
        const int st = it & 1;
        #pragma unroll
        for (int kk = 0; kk < BK; kk += 8) {
            uint32_t af[4], bf[4][2];
            {
                int mb = wm + gid;
                af[0] = As[st][mb][kk + tig];
                af[1] = As[st][mb + 8][kk + tig];
                af[2] = As[st][mb][kk + tig + 4];
                af[3] = As[st][mb + 8][kk + tig + 4];
            }
            #pragma unroll
            for (int nt = 0; nt < 4; nt++) {
                int nb = wn + nt * 8 + gid;
                bf[nt][0] = Bs[st][nb][kk + tig];
                bf[nt][1] = Bs[st][nb][kk + tig + 4];
            }
            #pragma unroll
            for (int nt = 0; nt < 4; nt++)
                mma_tf32(acc[nt], af, bf[nt]);
        }
        __syncthreads();
    }

    // epilogue: scale, store C, column-sum reduce
    float cs0[4], cs1[4];
    {
        int m = m0 + wm + gid;
        float iq0 = g_invq[m], iq1 = g_invq[m + 8];
        #pragma unroll
        for (int nt = 0; nt < 4; nt++) {
            int n = n0 + wn + nt * 8 + 2 * tig;
            float ik0 = g_invk[n], ik1 = g_invk[n + 1];
            float v0 = acc[nt][0] * iq0 * ik0;
            float v1 = acc[nt][1] * iq0 * ik1;
            float v2 = acc[nt][2] * iq1 * ik0;
            float v3 = acc[nt][3] * iq1 * ik1;
            C[(size_t)m * POOL + n]           = v0;
            C[(size_t)m * POOL + n + 1]       = v1;
            C[(size_t)(m + 8) * POOL + n]     = v2;
            C[(size_t)(m + 8) * POOL + n + 1] = v3;
            cs0[nt] = v0 + v2;
            cs1[nt] = v1 + v3;
        }
    }
    #pragma unroll
    for (int nt = 0; nt < 4; nt++) {
        float c0 = cs0[nt], c1 = cs1[nt];
        #pragma unroll
        for (int off = 4; off < 32; off <<= 1) {
            c0 += __shfl_xor_sync(0xffffffffu, c0, off);
            c1 += __shfl_xor_sync(0xffffffffu, c1, off);
        }
        if (gid == 0) {
            int n = n0 + wn + nt * 8 + 2 * tig;
            atomicAdd(&g_colsum[n], c0);
            atomicAdd(&g_colsum[n + 1], c1);
        }
    }
}

// ---------------- kernel 3: route + gather of E rows (fused) ----------------
// grid B_, 256 threads. warp0 scans top-8; 8 warps exact-recheck 1 cand each;
// thread0 picks top-4; then 8 warps stream 32 rows (16 Pk + 16 Pv) to output.
__global__ __launch_bounds__(256) void routegather_kernel(const float* __restrict__ C,
                                                          const float* __restrict__ xq,
                                                          const float* __restrict__ ek,
                                                          const float* __restrict__ e_p,
                                                          float* __restrict__ out) {
    const int row  = blockIdx.x;
    const int t    = threadIdx.x;
    const int lane = t & 31;
    const int w    = t >> 5;
    __shared__ int   s_cand[TOP8];
    __shared__ float s_ex[TOP8];
    __shared__ int   s_sel[TOPK];

    if (w == 0) {
        const float* crow = C + (size_t)row * POOL;
        float d[16];
        #pragma unroll
        for (int u = 0; u < 16; u++) d[u] = 1.0f - crow[u * 32 + lane];
        #pragma unroll
        for (int k = 0; k < TOP8; k++) {
            float best = INFINITY; int bi = 0x7fffffff;
            #pragma unroll
            for (int u = 0; u < 16; u++) {
                int p = u * 32 + lane;
                if (d[u] < best || (d[u] == best && p < bi)) { best = d[u]; bi = p; }
            }
            #pragma unroll
            for (int off = 16; off; off >>= 1) {
                float ov = __shfl_xor_sync(0xffffffffu, best, off);
                int   oi = __shfl_xor_sync(0xffffffffu, bi, off);
                if (ov < best || (ov == best && oi < bi)) { best = ov; bi = oi; }
            }
            if (lane == 0) s_cand[k] = bi;
            int ul = bi >> 5, ll = bi & 31;
            #pragma unroll
            for (int u = 0; u < 16; u++)
                if (u == ul && ll == lane) d[u] = INFINITY;
        }
    }
    __syncthreads();

    // exact fp32 recheck: warp w -> candidate w
    {
        int p = s_cand[w];
        const float4* q4 = (const float4*)(xq + (size_t)row * KEYD);
        const float4* k4 = (const float4*)(ek + (size_t)p * KEYD);
        float s = 0.f;
        #pragma unroll
        for (int i = 0; i < 6; i++) {
            float4 qv = q4[lane + 32 * i];
            float4 kv = k4[lane + 32 * i];
            s += qv.x * kv.x + qv.y * kv.y + qv.z * kv.z + qv.w * kv.w;
        }
        #pragma unroll
        for (int off = 16; off; off >>= 1) s += __shfl_xor_sync(0xffffffffu, s, off);
        if (lane == 0) s_ex[w] = 1.0f - s * g_invq[row] * g_invk[p];
    }
    __syncthreads();

    if (t == 0) {
        bool used[TOP8];
        #pragma unroll
        for (int c = 0; c < TOP8; c++) used[c] = false;
        #pragma unroll
        for (int k = 0; k < TOPK; k++) {
            float best = INFINITY; int bi = 0x7fffffff; int slot = 0;
            #pragma unroll
            for (int c = 0; c < TOP8; c++) {
                if (!used[c] && (s_ex[c] < best || (s_ex[c] == best && s_cand[c] < bi))) {
                    best = s_ex[c]; bi = s_cand[c]; slot = c;
                }
            }
            used[slot] = true;
            s_sel[k] = bi;
            atomicAdd(&g_cnt[bi], 1);
        }
    }
    __syncthreads();

    // gather: 32 row-copies (16 Pk + 16 Pv), warp w does copies w, w+8, w+16, w+24
    int p0 = s_sel[0], p1 = s_sel[1], p2 = s_sel[2], p3 = s_sel[3];
    #pragma unroll
    for (int j = 0; j < 4; j++) {
        int c = w + 8 * j;               // 0..31
        int isv = c >> 4;                // 0 = Pk, 1 = Pv
        int rr4 = c & 15;                // dest row 0..15
        int k   = rr4 >> 2;
        int rr  = rr4 & 3;
        int p   = (k == 0) ? p0 : (k == 1) ? p1 : (k == 2) ? p2 : p3;
        const float4* src = (const float4*)(e_p + ((size_t)p * EPL + isv * 4 + rr) * EMB);
        float4* dst = (float4*)(out + (size_t)isv * PV_OFF
                                + ((size_t)row * PK_ROWS + rr4) * EMB);
        #pragma unroll
        for (int i = 0; i < 6; i++)
            __stcs(dst + lane + 32 * i, src[lane + 32 * i]);
    }
}

// ---------------- kernel 4: static rows + x_block + loss/counts -------------
__global__ __launch_bounds__(256) void static_kernel(const float* __restrict__ g_p,
                                                     const float* __restrict__ xb,
                                                     float* __restrict__ out) {
    const int b = blockIdx.x;
    const int t = threadIdx.x;
    const int g = t >> 5;
    const int lane = t & 31;

    // G rows: warp g -> g_p row g (g<4: Pk rows 16..19; g>=4: Pv rows 16..19)
    {
        const float4* src = (const float4*)(g_p + (size_t)g * EMB);
        float4* dst = (g < 4)
            ? (float4*)(out + ((size_t)b * PK_ROWS + 16 + g) * EMB)
            : (float4*)(out + PV_OFF + ((size_t)b * PK_ROWS + 16 + (g - 4)) * EMB);
        #pragma unroll
        for (int i = 0; i < 6; i++)
            __stcs(dst + lane + 32 * i, src[lane + 32 * i]);
    }
    // x_block passthrough (dst only 4B-aligned -> scalar streaming stores)
    {
        const float* s = xb + (size_t)b * EMB;
        float* d = out + XB_OFF + (size_t)b * EMB;
        #pragma unroll
        for (int i = 0; i < 3; i++)
            __stcs(d + t + 256 * i, s[t + 256 * i]);
    }
    // loss + counts (block 0 only)
    if (b == 0) {
        __shared__ float s_w[8];
        float local = 0.f;
        #pragma unroll
        for (int rep = 0; rep < 2; rep++) {
            int p = t + rep * 256;
            int c = g_cnt[p];
            out[CNT_OFF + p] = (float)c;
            local += g_colsum[p] * (float)c;
        }
        #pragma unroll
        for (int off = 16; off; off >>= 1)
            local += __shfl_xor_sync(0xffffffffu, local, off);
        if (lane == 0) s_w[g] = local;
        __syncthreads();
        if (t == 0) {
            float tot = 0.f;
            #pragma unroll
            for (int i = 0; i < 8; i++) tot += s_w[i];
            out[LOSS_OFF] = 1.0f - tot / ((float)B_ * (float)B_ * (float)TOPK);
        }
    }
}

// ---------------- launch ----------------
extern "C" void kernel_launch(void* const* d_in, const int* in_sizes, int n_in,
                              void* d_out, int out_size) {
    const float* x_querry = (const float*)d_in[0];
    const float* x_block  = (const float*)d_in[1];
    const float* e_k      = (const float*)d_in[2];
    const float* e_p      = (const float*)d_in[3];
    const float* g_p      = (const float*)d_in[4];
    (void)in_sizes; (void)n_in; (void)out_size;

    float* out = (float*)d_out;
    float* d_C = nullptr;
    cudaGetSymbolAddress((void**)&d_C, g_C);

    prep_kernel<<<(B_ + POOL) / 8, 256>>>(x_querry, e_k);                      // 1
    gemm_tf32_kernel<<<dim3(POOL / BN, B_ / BM), 256>>>(x_querry, e_k, d_C);   // 2
    routegather_kernel<<<B_, 256>>>(d_C, x_querry, e_k, e_p, out);             // 3
    static_kernel<<<B_, 256>>>(g_p, x_block, out);                             // 4 (profiled)
}